// round 7
// baseline (speedup 1.0000x reference)
#include <cuda_runtime.h>
#include <cuda_fp16.h>
#include <cstdint>
#include <cstddef>

#define BN 1024
#define DD 768
#define TT 512
#define VV 49408

// ------------------------- static device workspace --------------------------
__device__ float g_kw[BN * TT];            // projected keywords fp32 (split-K accum)
__device__ float g_rowsum[BN];             // softmax denominators (scaled)
__device__ __half g_kwH[BN * TT];                  // normalized kw, fp16
__device__ __half g_embH[(size_t)VV * TT];         // NORMALIZED emb [v][t], fp16
__device__ __half g_embR[(size_t)VV * TT];         // RAW emb [v][t], fp16
__device__ __half g_probs[(size_t)BN * VV];        // scaled unnormalized probs, fp16

// ------------------------------ helpers -------------------------------------
__device__ __forceinline__ uint32_t smem_u32(const void* p) {
    uint32_t a;
    asm("{ .reg .u64 t; cvta.to.shared.u64 t, %1; cvt.u32.u64 %0, t; }"
        : "=r"(a) : "l"(p));
    return a;
}
__device__ __forceinline__ void cp16(uint32_t s, const void* g) {
    asm volatile("cp.async.cg.shared.global [%0], [%1], 16;" :: "r"(s), "l"(g));
}
__device__ __forceinline__ void ldsm4(uint32_t* r, uint32_t addr) {
    asm volatile("ldmatrix.sync.aligned.m8n8.x4.shared.b16 {%0,%1,%2,%3}, [%4];"
        : "=r"(r[0]), "=r"(r[1]), "=r"(r[2]), "=r"(r[3]) : "r"(addr));
}
__device__ __forceinline__ void ldsm4t(uint32_t* r, uint32_t addr) {
    asm volatile("ldmatrix.sync.aligned.m8n8.x4.trans.shared.b16 {%0,%1,%2,%3}, [%4];"
        : "=r"(r[0]), "=r"(r[1]), "=r"(r[2]), "=r"(r[3]) : "r"(addr));
}
__device__ __forceinline__ void mma16816(float* c, const uint32_t* a, const uint32_t* b) {
    asm volatile("mma.sync.aligned.m16n8k16.row.col.f32.f16.f16.f32 "
        "{%0,%1,%2,%3}, {%4,%5,%6,%7}, {%8,%9}, {%0,%1,%2,%3};"
        : "+f"(c[0]), "+f"(c[1]), "+f"(c[2]), "+f"(c[3])
        : "r"(a[0]), "r"(a[1]), "r"(a[2]), "r"(a[3]), "r"(b[0]), "r"(b[1]));
}
// fp16-accumulate variant (half-rate path hypothesis)
__device__ __forceinline__ void mma16816h(uint32_t* c, const uint32_t* a, const uint32_t* b) {
    asm volatile("mma.sync.aligned.m16n8k16.row.col.f16.f16.f16.f16 "
        "{%0,%1}, {%2,%3,%4,%5}, {%6,%7}, {%0,%1};"
        : "+r"(c[0]), "+r"(c[1])
        : "r"(a[0]), "r"(a[1]), "r"(a[2]), "r"(a[3]), "r"(b[0]), "r"(b[1]));
}
__device__ __forceinline__ uint32_t pack2h(__half a, __half b) {
    return (uint32_t)__half_as_ushort(a) | ((uint32_t)__half_as_ushort(b) << 16);
}

// smem: A plane 128x144B; B plane: EPI0 128x144B, EPI1 64x272B (both <= 18432)
#define ROWA   144
#define ROWBT  272
#define PLANE  18432
#define STAGE  (2 * PLANE)       // 36864
#define NSTAGE 3
#define SMEMSZ (NSTAGE * STAGE)  // 110592 -> 2 CTAs/SM

// =============================================================================
// fp16 warp-MMA GEMM, CTA tile 128x128, BK=64, 256 thr, warp tile 64x32.
// EPI==0: fp32-acc MMA; logits -> exp epilogue -> fp16 probs + rowsum atomics
// EPI==1: fp16-acc MMA (per-chunk fp32 promotion); split-K -> atomicAdd out
// =============================================================================
template<int EPI>
__global__ __launch_bounds__(256, 2) void mma_gemm(float* __restrict__ outf)
{
    constexpr uint32_t LDA = (EPI == 0) ? TT : VV;   // A stride (elements)
    extern __shared__ char smem[];
    const uint32_t sbase = smem_u32(smem);
    const int tid = threadIdx.x;
    const int lane = tid & 31, wid = tid >> 5;
    const int warpM = wid & 1, warpN = wid >> 1;

    const __half *A, *B;
    int m0, n0, c0, c1;
    if (EPI == 0) {
        A = g_kwH; B = g_embH;
        m0 = blockIdx.x * 128; n0 = blockIdx.y * 128;
        c0 = 0; c1 = TT / 64;
    } else {
        A = g_probs; B = g_embR;
        n0 = blockIdx.x * 128; m0 = blockIdx.y * 128;
        const long tot = VV / 64;
        c0 = (int)((tot * blockIdx.z) / gridDim.z);
        c1 = (int)((tot * (blockIdx.z + 1)) / gridDim.z);
    }
    const int nch = c1 - c0;

    // ---- loader thread geometry (32-bit offsets, constexpr strides) ----
    const uint32_t ch   = tid & 7;
    const uint32_t rowA = tid >> 3;
    uint32_t aOff = (uint32_t)(m0 + rowA) * LDA + (uint32_t)c0 * 64 + ch * 8;
    const uint32_t aSo = rowA * ROWA + ch * 16;
    uint32_t bOff, bSo;
    if (EPI == 0) {
        bOff = (uint32_t)(n0 + rowA) * TT + (uint32_t)c0 * 64 + ch * 8;
        bSo  = aSo;
    } else {
        const uint32_t rb = tid >> 4, cb = tid & 15;   // 64 rows x 256B
        bOff = ((uint32_t)c0 * 64 + rb) * TT + (uint32_t)n0 + cb * 8;
        bSo  = rb * ROWBT + cb * 16;
    }

    auto issue = [&](uint32_t st) {
        #pragma unroll
        for (int p = 0; p < 4; p++) {
            cp16(st + aSo + p * (32 * ROWA), A + aOff + p * (32 * LDA));
            if (EPI == 0)
                cp16(st + PLANE + bSo + p * (32 * ROWA), B + bOff + p * (32 * TT));
            else
                cp16(st + PLANE + bSo + p * (16 * ROWBT), B + bOff + p * (16 * TT));
        }
        aOff += 64;
        bOff += (EPI == 0) ? 64 : 64 * TT;
    };

    // ---- compute fragment smem bases ----
    const uint32_t saOff = (uint32_t)(warpM * 64 + (lane & 15)) * ROWA + ((lane >> 4) << 4);
    uint32_t sbOff;
    if (EPI == 0)
        sbOff = PLANE + (uint32_t)(warpN * 32 + (lane & 15)) * ROWA + ((lane >> 4) << 4);
    else
        sbOff = PLANE + (uint32_t)((lane & 7) + ((lane >> 4) << 3)) * ROWBT
              + (uint32_t)(warpN * 32 + ((lane >> 3) & 1) * 8) * 2;

    float acc[4][4][4];
    #pragma unroll
    for (int i = 0; i < 4; i++)
        #pragma unroll
        for (int j = 0; j < 4; j++)
            #pragma unroll
            for (int k = 0; k < 4; k++) acc[i][j][k] = 0.f;

    // ---- prologue: 2 stages in flight ----
    issue(sbase);
    asm volatile("cp.async.commit_group;" ::: "memory");
    issue(sbase + STAGE);
    asm volatile("cp.async.commit_group;" ::: "memory");

    int buf = 0;

    for (int c = 0; c < nch; c++) {
        asm volatile("cp.async.wait_group 1;" ::: "memory");
        __syncthreads();
        const uint32_t st = sbase + (uint32_t)buf * STAGE;
        int nbuf = buf + 2; if (nbuf >= NSTAGE) nbuf -= NSTAGE;
        if (c + 2 < nch) issue(sbase + (uint32_t)nbuf * STAGE);
        asm volatile("cp.async.commit_group;" ::: "memory");

        if (EPI == 0) {
            // ---- fp32-acc path with ks fragment double-buffer ----
            uint32_t a[2][4][4], b[2][2][4];
            #pragma unroll
            for (int mf = 0; mf < 4; mf++)
                ldsm4(a[0][mf], st + saOff + mf * (16 * ROWA));
            #pragma unroll
            for (int g = 0; g < 2; g++)
                ldsm4(b[0][g], st + sbOff + g * (16 * ROWA));
            #pragma unroll
            for (int ks = 0; ks < 4; ks++) {
                const int cur = ks & 1, nxt = cur ^ 1;
                if (ks < 3) {
                    const uint32_t ko = (ks + 1) * 32;
                    #pragma unroll
                    for (int mf = 0; mf < 4; mf++)
                        ldsm4(a[nxt][mf], st + saOff + mf * (16 * ROWA) + ko);
                    #pragma unroll
                    for (int g = 0; g < 2; g++)
                        ldsm4(b[nxt][g], st + sbOff + g * (16 * ROWA) + ko);
                }
                #pragma unroll
                for (int mf = 0; mf < 4; mf++)
                    #pragma unroll
                    for (int nf = 0; nf < 4; nf++) {
                        uint32_t bf[2] = { b[cur][nf >> 1][nf & 1],
                                           b[cur][nf >> 1][2 + (nf & 1)] };
                        mma16816(acc[mf][nf], a[cur][mf], bf);
                    }
            }
        } else {
            // ---- fp16-acc path: accumulate chunk in fp16, promote once ----
            uint32_t hacc[4][4][2];
            #pragma unroll
            for (int i = 0; i < 4; i++)
                #pragma unroll
                for (int j = 0; j < 4; j++) { hacc[i][j][0] = 0u; hacc[i][j][1] = 0u; }
            #pragma unroll
            for (int ks = 0; ks < 4; ks++) {
                uint32_t a[4][4], b[2][4];
                const uint32_t ko = ks * 32;
                #pragma unroll
                for (int mf = 0; mf < 4; mf++)
                    ldsm4(a[mf], st + saOff + mf * (16 * ROWA) + ko);
                #pragma unroll
                for (int g = 0; g < 2; g++)
                    ldsm4t(b[g], st + sbOff + ks * (16 * ROWBT) + g * 32);
                #pragma unroll
                for (int mf = 0; mf < 4; mf++)
                    #pragma unroll
                    for (int nf = 0; nf < 4; nf++) {
                        uint32_t bf[2] = { b[nf >> 1][nf & 1],
                                           b[nf >> 1][2 + (nf & 1)] };
                        mma16816h(hacc[mf][nf], a[mf], bf);
                    }
            }
            #pragma unroll
            for (int mf = 0; mf < 4; mf++)
                #pragma unroll
                for (int nf = 0; nf < 4; nf++) {
                    const float2 f0 = __half22float2(
                        *reinterpret_cast<__half2*>(&hacc[mf][nf][0]));
                    const float2 f1 = __half22float2(
                        *reinterpret_cast<__half2*>(&hacc[mf][nf][1]));
                    acc[mf][nf][0] += f0.x;  acc[mf][nf][1] += f0.y;
                    acc[mf][nf][2] += f1.x;  acc[mf][nf][3] += f1.y;
                }
        }
        if (++buf >= NSTAGE) buf = 0;
    }

    if (EPI == 0) {
        #pragma unroll
        for (int mf = 0; mf < 4; mf++) {
            const int r0 = m0 + warpM * 64 + mf * 16 + (lane >> 2);
            float rs0 = 0.f, rs1 = 0.f;
            #pragma unroll
            for (int nf = 0; nf < 4; nf++) {
                const int cb = n0 + warpN * 32 + nf * 8 + (lane & 3) * 2;
                // p = exp(10*cos - 10) * 4096  (scale cancels in normalization)
                const float e0 = __expf(acc[mf][nf][0] * 10.f - 10.f) * 4096.f;
                const float e1 = __expf(acc[mf][nf][1] * 10.f - 10.f) * 4096.f;
                const float e2 = __expf(acc[mf][nf][2] * 10.f - 10.f) * 4096.f;
                const float e3 = __expf(acc[mf][nf][3] * 10.f - 10.f) * 4096.f;
                rs0 += e0 + e1;  rs1 += e2 + e3;
                *(uint32_t*)&g_probs[(size_t)r0 * VV + cb] =
                    pack2h(__float2half_rn(e0), __float2half_rn(e1));
                *(uint32_t*)&g_probs[(size_t)(r0 + 8) * VV + cb] =
                    pack2h(__float2half_rn(e2), __float2half_rn(e3));
            }
            rs0 += __shfl_xor_sync(0xffffffffu, rs0, 1);
            rs0 += __shfl_xor_sync(0xffffffffu, rs0, 2);
            rs1 += __shfl_xor_sync(0xffffffffu, rs1, 1);
            rs1 += __shfl_xor_sync(0xffffffffu, rs1, 2);
            if ((lane & 3) == 0) {
                atomicAdd(&g_rowsum[r0],     rs0);
                atomicAdd(&g_rowsum[r0 + 8], rs1);
            }
        }
    } else {
        #pragma unroll
        for (int mf = 0; mf < 4; mf++) {
            const int r0 = m0 + warpM * 64 + mf * 16 + (lane >> 2);
            const float s0 = 1.f / g_rowsum[r0];
            const float s1 = 1.f / g_rowsum[r0 + 8];
            #pragma unroll
            for (int nf = 0; nf < 4; nf++) {
                const int cb = n0 + warpN * 32 + nf * 8 + (lane & 3) * 2;
                atomicAdd(&outf[(size_t)r0 * TT + cb],           acc[mf][nf][0] * s0);
                atomicAdd(&outf[(size_t)r0 * TT + cb + 1],       acc[mf][nf][1] * s0);
                atomicAdd(&outf[(size_t)(r0 + 8) * TT + cb],     acc[mf][nf][2] * s1);
                atomicAdd(&outf[(size_t)(r0 + 8) * TT + cb + 1], acc[mf][nf][3] * s1);
            }
        }
    }
}

// =============================================================================
// fp32 SIMT projection GEMM, split-K z=4 (128 CTAs): kw += audio @ W
// =============================================================================
__global__ __launch_bounds__(256, 2)
void proj_gemm(const float* __restrict__ A, const float* __restrict__ B,
               float* __restrict__ C)
{
    __shared__ float As[16][132];
    __shared__ float Bs[16][132];
    const int tid = threadIdx.x;
    const int m0 = blockIdx.y * 128, n0 = blockIdx.x * 128;
    const int kb = blockIdx.z * (DD / 4), ke = kb + DD / 4;
    const int tx = tid & 15, ty = tid >> 4;
    const int a_row = tid >> 2, a_c4 = (tid & 3) * 4;
    const int b_k = tid >> 5, b_n4 = (tid & 31) * 4;

    float acc[8][8];
    #pragma unroll
    for (int i = 0; i < 8; i++)
        #pragma unroll
        for (int j = 0; j < 8; j++) acc[i][j] = 0.f;

    for (int k0 = kb; k0 < ke; k0 += 16) {
        float4 va0 = *(const float4*)&A[(size_t)(m0 + a_row)      * DD + k0 + a_c4];
        float4 va1 = *(const float4*)&A[(size_t)(m0 + a_row + 64) * DD + k0 + a_c4];
        As[a_c4 + 0][a_row] = va0.x;  As[a_c4 + 1][a_row] = va0.y;
        As[a_c4 + 2][a_row] = va0.z;  As[a_c4 + 3][a_row] = va0.w;
        As[a_c4 + 0][a_row + 64] = va1.x;  As[a_c4 + 1][a_row + 64] = va1.y;
        As[a_c4 + 2][a_row + 64] = va1.z;  As[a_c4 + 3][a_row + 64] = va1.w;
        *(float4*)&Bs[b_k][b_n4]     = *(const float4*)&B[(size_t)(k0 + b_k)     * TT + n0 + b_n4];
        *(float4*)&Bs[b_k + 8][b_n4] = *(const float4*)&B[(size_t)(k0 + b_k + 8) * TT + n0 + b_n4];
        __syncthreads();
        #pragma unroll
        for (int kk = 0; kk < 16; kk++) {
            float a[8], b[8];
            *(float4*)&a[0] = *(const float4*)&As[kk][ty * 8];
            *(float4*)&a[4] = *(const float4*)&As[kk][ty * 8 + 4];
            *(float4*)&b[0] = *(const float4*)&Bs[kk][tx * 8];
            *(float4*)&b[4] = *(const float4*)&Bs[kk][tx * 8 + 4];
            #pragma unroll
            for (int i = 0; i < 8; i++)
                #pragma unroll
                for (int j = 0; j < 8; j++)
                    acc[i][j] = fmaf(a[i], b[j], acc[i][j]);
        }
        __syncthreads();
    }
    #pragma unroll
    for (int i = 0; i < 8; i++) {
        const int m = m0 + ty * 8 + i;
        #pragma unroll
        for (int j = 0; j < 8; j++)
            atomicAdd(&C[(size_t)m * TT + n0 + tx * 8 + j], acc[i][j]);
    }
}

// kw rows: add bias, L2-normalize, write fp16
__global__ void kw_norm_pack(const float* __restrict__ bias)
{
    const int w    = (blockIdx.x * blockDim.x + threadIdx.x) >> 5;
    const int lane = threadIdx.x & 31;
    if (w >= BN) return;
    const float4* row = (const float4*)(g_kw + (size_t)w * TT);
    const float4* b4  = (const float4*)bias;
    float4 v[4];
    float ss = 0.f;
    #pragma unroll
    for (int q = 0; q < 4; q++) {
        v[q] = row[lane + 32 * q];
        const float4 bb = b4[lane + 32 * q];
        v[q].x += bb.x; v[q].y += bb.y; v[q].z += bb.z; v[q].w += bb.w;
        ss += v[q].x * v[q].x + v[q].y * v[q].y + v[q].z * v[q].z + v[q].w * v[q].w;
    }
    #pragma unroll
    for (int o = 16; o > 0; o >>= 1) ss += __shfl_xor_sync(0xffffffffu, ss, o);
    const float inv = 1.f / fmaxf(sqrtf(ss), 1e-8f);
    #pragma unroll
    for (int q = 0; q < 4; q++) {
        const int e0 = (lane + 32 * q) * 4;
        *(uint32_t*)&g_kwH[(size_t)w * TT + e0] =
            pack2h(__float2half_rn(v[q].x * inv), __float2half_rn(v[q].y * inv));
        *(uint32_t*)&g_kwH[(size_t)w * TT + e0 + 2] =
            pack2h(__float2half_rn(v[q].z * inv), __float2half_rn(v[q].w * inv));
    }
}

// fused emb prep: one warp per vocab row; read fp32 once,
// write normalized fp16 (embH) + raw fp16 (embR).
__global__ void emb_prep(const float* __restrict__ emb)
{
    const int w    = (blockIdx.x * blockDim.x + threadIdx.x) >> 5;
    const int lane = threadIdx.x & 31;
    if (w >= VV) return;
    const float4* row = (const float4*)(emb + (size_t)w * TT);
    float4 v[4];
    float ss = 0.f;
    #pragma unroll
    for (int q = 0; q < 4; q++) {
        v[q] = row[lane + 32 * q];
        ss += v[q].x * v[q].x + v[q].y * v[q].y + v[q].z * v[q].z + v[q].w * v[q].w;
    }
    #pragma unroll
    for (int o = 16; o > 0; o >>= 1) ss += __shfl_xor_sync(0xffffffffu, ss, o);
    const float inv = 1.f / fmaxf(sqrtf(ss), 1e-8f);
    #pragma unroll
    for (int q = 0; q < 4; q++) {
        const int e0 = (lane + 32 * q) * 4;
        *(uint32_t*)&g_embR[(size_t)w * TT + e0] =
            pack2h(__float2half_rn(v[q].x), __float2half_rn(v[q].y));
        *(uint32_t*)&g_embR[(size_t)w * TT + e0 + 2] =
            pack2h(__float2half_rn(v[q].z), __float2half_rn(v[q].w));
        *(uint32_t*)&g_embH[(size_t)w * TT + e0] =
            pack2h(__float2half_rn(v[q].x * inv), __float2half_rn(v[q].y * inv));
        *(uint32_t*)&g_embH[(size_t)w * TT + e0 + 2] =
            pack2h(__float2half_rn(v[q].z * inv), __float2half_rn(v[q].w * inv));
    }
}

// =============================================================================
extern "C" void kernel_launch(void* const* d_in, const int* in_sizes, int n_in,
                              void* d_out, int out_size)
{
    const float* audio = (const float*)d_in[0];
    const float* W     = (const float*)d_in[1];
    const float* bias  = (const float*)d_in[2];
    const float* emb   = (const float*)d_in[3];
    float* out = (float*)d_out;

    cudaFuncSetAttribute(mma_gemm<0>, cudaFuncAttributeMaxDynamicSharedMemorySize, SMEMSZ);
    cudaFuncSetAttribute(mma_gemm<1>, cudaFuncAttributeMaxDynamicSharedMemorySize, SMEMSZ);

    float *kw, *rowsum;
    cudaGetSymbolAddress((void**)&kw,     g_kw);
    cudaGetSymbolAddress((void**)&rowsum, g_rowsum);

    cudaMemsetAsync(kw,     0, (size_t)BN * TT * sizeof(float), 0);
    cudaMemsetAsync(rowsum, 0, BN * sizeof(float), 0);
    cudaMemsetAsync(out,    0, (size_t)out_size * sizeof(float), 0);

    proj_gemm<<<dim3(TT / 128, BN / 128, 4), 256>>>(audio, W, kw);
    kw_norm_pack<<<BN / 8, 256>>>(bias);
    emb_prep<<<VV / 8, 256>>>(emb);

    // GEMM1: logits + exp epilogue (fp32-acc control)
    mma_gemm<0><<<dim3(BN / 128, VV / 128), 256, SMEMSZ>>>(nullptr);
    // GEMM2: fp16-acc test; x = n-tiles (4), y = m-tiles (8), z = split-K (9)
    mma_gemm<1><<<dim3(TT / 128, BN / 128, 9), 256, SMEMSZ>>>(out);
}

// round 8
// speedup vs baseline: 1.0322x; 1.0322x over previous
#include <cuda_runtime.h>
#include <cuda_fp16.h>
#include <cstdint>
#include <cstddef>

#define BN 1024
#define DD 768
#define TT 512
#define VV 49408

// ------------------------- static device workspace --------------------------
__device__ float g_kw[BN * TT];            // projected keywords fp32 (split-K accum)
__device__ float g_rowsum[BN];             // softmax denominators (scaled)
__device__ __half g_kwH[BN * TT];                  // normalized kw, fp16
__device__ __half g_embH[(size_t)VV * TT];         // NORMALIZED emb [v][t], fp16
__device__ __half g_embR[(size_t)VV * TT];         // RAW emb [v][t], fp16
__device__ __half g_probs[(size_t)BN * VV];        // scaled unnormalized probs, fp16

// ------------------------------ helpers -------------------------------------
__device__ __forceinline__ uint32_t smem_u32(const void* p) {
    uint32_t a;
    asm("{ .reg .u64 t; cvta.to.shared.u64 t, %1; cvt.u32.u64 %0, t; }"
        : "=r"(a) : "l"(p));
    return a;
}
__device__ __forceinline__ void cp16(uint32_t s, const void* g) {
    asm volatile("cp.async.cg.shared.global [%0], [%1], 16;" :: "r"(s), "l"(g));
}
__device__ __forceinline__ void ldsm4(uint32_t* r, uint32_t addr) {
    asm volatile("ldmatrix.sync.aligned.m8n8.x4.shared.b16 {%0,%1,%2,%3}, [%4];"
        : "=r"(r[0]), "=r"(r[1]), "=r"(r[2]), "=r"(r[3]) : "r"(addr));
}
__device__ __forceinline__ void ldsm4t(uint32_t* r, uint32_t addr) {
    asm volatile("ldmatrix.sync.aligned.m8n8.x4.trans.shared.b16 {%0,%1,%2,%3}, [%4];"
        : "=r"(r[0]), "=r"(r[1]), "=r"(r[2]), "=r"(r[3]) : "r"(addr));
}
__device__ __forceinline__ void mma16816(float* c, const uint32_t* a, const uint32_t* b) {
    asm volatile("mma.sync.aligned.m16n8k16.row.col.f32.f16.f16.f32 "
        "{%0,%1,%2,%3}, {%4,%5,%6,%7}, {%8,%9}, {%0,%1,%2,%3};"
        : "+f"(c[0]), "+f"(c[1]), "+f"(c[2]), "+f"(c[3])
        : "r"(a[0]), "r"(a[1]), "r"(a[2]), "r"(a[3]), "r"(b[0]), "r"(b[1]));
}
__device__ __forceinline__ uint32_t pack2h(__half a, __half b) {
    return (uint32_t)__half_as_ushort(a) | ((uint32_t)__half_as_ushort(b) << 16);
}

// smem: A plane 128x144B; B plane: EPI0 128x144B, EPI1 64x272B (both <= 18432)
#define ROWA   144
#define ROWBT  272
#define PLANE  18432
#define STAGE  (2 * PLANE)       // 36864
#define NSTAGE 2
#define SMEMSZ (NSTAGE * STAGE)  // 73728 -> 2 CTAs/SM (147KB)

// =============================================================================
// fp16 warp-MMA GEMM, CTA tile 128x128, BK=64, 512 thr, 16 warps, warp 32x32.
// fp32 accumulate. 2-stage cp.async double buffer.
// EPI==0: logits -> exp epilogue -> scaled fp16 probs + rowsum atomics
// EPI==1: VQ GEMM split-K (B via ldmatrix.trans on K-major emb) -> atomicAdd out
// =============================================================================
template<int EPI>
__global__ __launch_bounds__(512, 2) void mma_gemm(float* __restrict__ outf)
{
    constexpr uint32_t LDA = (EPI == 0) ? TT : VV;   // A stride (elements)
    extern __shared__ char smem[];
    const uint32_t sbase = smem_u32(smem);
    const int tid = threadIdx.x;
    const int lane = tid & 31, wid = tid >> 5;      // wid 0..15
    const int warpM = wid & 3, warpN = wid >> 2;    // 4 x 4 warp grid, 32x32 tiles

    const __half *A, *B;
    int m0, n0, c0, c1;
    if (EPI == 0) {
        A = g_kwH; B = g_embH;
        m0 = blockIdx.x * 128; n0 = blockIdx.y * 128;
        c0 = 0; c1 = TT / 64;
    } else {
        A = g_probs; B = g_embR;
        n0 = blockIdx.x * 128; m0 = blockIdx.y * 128;
        const long tot = VV / 64;
        c0 = (int)((tot * blockIdx.z) / gridDim.z);
        c1 = (int)((tot * (blockIdx.z + 1)) / gridDim.z);
    }
    const int nch = c1 - c0;

    // ---- loader thread geometry (512 threads, 32-bit offsets) ----
    const uint32_t ch   = tid & 7;           // 16B chunk within 64-elem row piece
    const uint32_t rowA = tid >> 3;          // 0..63, second half via +64
    uint32_t aOff = (uint32_t)(m0 + rowA) * LDA + (uint32_t)c0 * 64 + ch * 8;
    const uint32_t aSo = rowA * ROWA + ch * 16;
    uint32_t bOff, bSo;
    if (EPI == 0) {
        bOff = (uint32_t)(n0 + rowA) * TT + (uint32_t)c0 * 64 + ch * 8;
        bSo  = aSo;
    } else {
        const uint32_t rb = tid >> 4, cb = tid & 15;   // 64 rows x 256B, 2 passes of 32
        bOff = ((uint32_t)c0 * 64 + rb) * TT + (uint32_t)n0 + cb * 8;
        bSo  = rb * ROWBT + cb * 16;
    }

    auto issue = [&](uint32_t st) {
        #pragma unroll
        for (int p = 0; p < 2; p++) {
            cp16(st + aSo + p * (64 * ROWA), A + aOff + p * (64 * LDA));
            if (EPI == 0)
                cp16(st + PLANE + bSo + p * (64 * ROWA), B + bOff + p * (64 * TT));
            else
                cp16(st + PLANE + bSo + p * (32 * ROWBT), B + bOff + p * (32 * TT));
        }
        aOff += 64;
        bOff += (EPI == 0) ? 64 : 64 * TT;
    };

    // ---- compute fragment smem bases ----
    const uint32_t saOff = (uint32_t)(warpM * 32 + (lane & 15)) * ROWA + ((lane >> 4) << 4);
    uint32_t sbOff;
    if (EPI == 0)
        sbOff = PLANE + (uint32_t)(warpN * 32 + (lane & 15)) * ROWA + ((lane >> 4) << 4);
    else
        sbOff = PLANE + (uint32_t)((lane & 7) + ((lane >> 4) << 3)) * ROWBT
              + (uint32_t)(warpN * 32 + ((lane >> 3) & 1) * 8) * 2;

    float acc[2][4][4];
    #pragma unroll
    for (int i = 0; i < 2; i++)
        #pragma unroll
        for (int j = 0; j < 4; j++)
            #pragma unroll
            for (int k = 0; k < 4; k++) acc[i][j][k] = 0.f;

    // ---- prologue: 2 stages in flight ----
    issue(sbase);
    asm volatile("cp.async.commit_group;" ::: "memory");
    issue(sbase + STAGE);
    asm volatile("cp.async.commit_group;" ::: "memory");

    for (int c = 0; c < nch; c++) {
        asm volatile("cp.async.wait_group 1;" ::: "memory");
        __syncthreads();
        const uint32_t st = sbase + (uint32_t)(c & 1) * STAGE;

        #pragma unroll
        for (int ks = 0; ks < 4; ks++) {
            const uint32_t ko = ks * 32;
            uint32_t a[2][4], b[2][4];
            #pragma unroll
            for (int mf = 0; mf < 2; mf++)
                ldsm4(a[mf], st + saOff + mf * (16 * ROWA) + ko);
            if (EPI == 0) {
                #pragma unroll
                for (int g = 0; g < 2; g++)
                    ldsm4(b[g], st + sbOff + g * (16 * ROWA) + ko);
            } else {
                #pragma unroll
                for (int g = 0; g < 2; g++)
                    ldsm4t(b[g], st + sbOff + ks * (16 * ROWBT) + g * 32);
            }
            #pragma unroll
            for (int mf = 0; mf < 2; mf++)
                #pragma unroll
                for (int nf = 0; nf < 4; nf++) {
                    uint32_t bf[2] = { b[nf >> 1][nf & 1],
                                       b[nf >> 1][2 + (nf & 1)] };
                    mma16816(acc[mf][nf], a[mf], bf);
                }
        }
        __syncthreads();
        if (c + 2 < nch) issue(st);
        asm volatile("cp.async.commit_group;" ::: "memory");
    }

    if (EPI == 0) {
        #pragma unroll
        for (int mf = 0; mf < 2; mf++) {
            const int r0 = m0 + warpM * 32 + mf * 16 + (lane >> 2);
            float rs0 = 0.f, rs1 = 0.f;
            #pragma unroll
            for (int nf = 0; nf < 4; nf++) {
                const int cb = n0 + warpN * 32 + nf * 8 + (lane & 3) * 2;
                // p = exp(10*cos - 10) * 4096  (scale cancels in normalization)
                const float e0 = __expf(acc[mf][nf][0] * 10.f - 10.f) * 4096.f;
                const float e1 = __expf(acc[mf][nf][1] * 10.f - 10.f) * 4096.f;
                const float e2 = __expf(acc[mf][nf][2] * 10.f - 10.f) * 4096.f;
                const float e3 = __expf(acc[mf][nf][3] * 10.f - 10.f) * 4096.f;
                rs0 += e0 + e1;  rs1 += e2 + e3;
                *(uint32_t*)&g_probs[(size_t)r0 * VV + cb] =
                    pack2h(__float2half_rn(e0), __float2half_rn(e1));
                *(uint32_t*)&g_probs[(size_t)(r0 + 8) * VV + cb] =
                    pack2h(__float2half_rn(e2), __float2half_rn(e3));
            }
            rs0 += __shfl_xor_sync(0xffffffffu, rs0, 1);
            rs0 += __shfl_xor_sync(0xffffffffu, rs0, 2);
            rs1 += __shfl_xor_sync(0xffffffffu, rs1, 1);
            rs1 += __shfl_xor_sync(0xffffffffu, rs1, 2);
            if ((lane & 3) == 0) {
                atomicAdd(&g_rowsum[r0],     rs0);
                atomicAdd(&g_rowsum[r0 + 8], rs1);
            }
        }
    } else {
        #pragma unroll
        for (int mf = 0; mf < 2; mf++) {
            const int r0 = m0 + warpM * 32 + mf * 16 + (lane >> 2);
            const float s0 = 1.f / g_rowsum[r0];
            const float s1 = 1.f / g_rowsum[r0 + 8];
            #pragma unroll
            for (int nf = 0; nf < 4; nf++) {
                const int cb = n0 + warpN * 32 + nf * 8 + (lane & 3) * 2;
                atomicAdd(&outf[(size_t)r0 * TT + cb],           acc[mf][nf][0] * s0);
                atomicAdd(&outf[(size_t)r0 * TT + cb + 1],       acc[mf][nf][1] * s0);
                atomicAdd(&outf[(size_t)(r0 + 8) * TT + cb],     acc[mf][nf][2] * s1);
                atomicAdd(&outf[(size_t)(r0 + 8) * TT + cb + 1], acc[mf][nf][3] * s1);
            }
        }
    }
}

// =============================================================================
// fp32 SIMT projection GEMM, split-K z=4 (128 CTAs): kw += audio @ W
// =============================================================================
__global__ __launch_bounds__(256, 2)
void proj_gemm(const float* __restrict__ A, const float* __restrict__ B,
               float* __restrict__ C)
{
    __shared__ float As[16][132];
    __shared__ float Bs[16][132];
    const int tid = threadIdx.x;
    const int m0 = blockIdx.y * 128, n0 = blockIdx.x * 128;
    const int kb = blockIdx.z * (DD / 4), ke = kb + DD / 4;
    const int tx = tid & 15, ty = tid >> 4;
    const int a_row = tid >> 2, a_c4 = (tid & 3) * 4;
    const int b_k = tid >> 5, b_n4 = (tid & 31) * 4;

    float acc[8][8];
    #pragma unroll
    for (int i = 0; i < 8; i++)
        #pragma unroll
        for (int j = 0; j < 8; j++) acc[i][j] = 0.f;

    for (int k0 = kb; k0 < ke; k0 += 16) {
        float4 va0 = *(const float4*)&A[(size_t)(m0 + a_row)      * DD + k0 + a_c4];
        float4 va1 = *(const float4*)&A[(size_t)(m0 + a_row + 64) * DD + k0 + a_c4];
        As[a_c4 + 0][a_row] = va0.x;  As[a_c4 + 1][a_row] = va0.y;
        As[a_c4 + 2][a_row] = va0.z;  As[a_c4 + 3][a_row] = va0.w;
        As[a_c4 + 0][a_row + 64] = va1.x;  As[a_c4 + 1][a_row + 64] = va1.y;
        As[a_c4 + 2][a_row + 64] = va1.z;  As[a_c4 + 3][a_row + 64] = va1.w;
        *(float4*)&Bs[b_k][b_n4]     = *(const float4*)&B[(size_t)(k0 + b_k)     * TT + n0 + b_n4];
        *(float4*)&Bs[b_k + 8][b_n4] = *(const float4*)&B[(size_t)(k0 + b_k + 8) * TT + n0 + b_n4];
        __syncthreads();
        #pragma unroll
        for (int kk = 0; kk < 16; kk++) {
            float a[8], b[8];
            *(float4*)&a[0] = *(const float4*)&As[kk][ty * 8];
            *(float4*)&a[4] = *(const float4*)&As[kk][ty * 8 + 4];
            *(float4*)&b[0] = *(const float4*)&Bs[kk][tx * 8];
            *(float4*)&b[4] = *(const float4*)&Bs[kk][tx * 8 + 4];
            #pragma unroll
            for (int i = 0; i < 8; i++)
                #pragma unroll
                for (int j = 0; j < 8; j++)
                    acc[i][j] = fmaf(a[i], b[j], acc[i][j]);
        }
        __syncthreads();
    }
    #pragma unroll
    for (int i = 0; i < 8; i++) {
        const int m = m0 + ty * 8 + i;
        #pragma unroll
        for (int j = 0; j < 8; j++)
            atomicAdd(&C[(size_t)m * TT + n0 + tx * 8 + j], acc[i][j]);
    }
}

// kw rows: add bias, L2-normalize, write fp16
__global__ void kw_norm_pack(const float* __restrict__ bias)
{
    const int w    = (blockIdx.x * blockDim.x + threadIdx.x) >> 5;
    const int lane = threadIdx.x & 31;
    if (w >= BN) return;
    const float4* row = (const float4*)(g_kw + (size_t)w * TT);
    const float4* b4  = (const float4*)bias;
    float4 v[4];
    float ss = 0.f;
    #pragma unroll
    for (int q = 0; q < 4; q++) {
        v[q] = row[lane + 32 * q];
        const float4 bb = b4[lane + 32 * q];
        v[q].x += bb.x; v[q].y += bb.y; v[q].z += bb.z; v[q].w += bb.w;
        ss += v[q].x * v[q].x + v[q].y * v[q].y + v[q].z * v[q].z + v[q].w * v[q].w;
    }
    #pragma unroll
    for (int o = 16; o > 0; o >>= 1) ss += __shfl_xor_sync(0xffffffffu, ss, o);
    const float inv = 1.f / fmaxf(sqrtf(ss), 1e-8f);
    #pragma unroll
    for (int q = 0; q < 4; q++) {
        const int e0 = (lane + 32 * q) * 4;
        *(uint32_t*)&g_kwH[(size_t)w * TT + e0] =
            pack2h(__float2half_rn(v[q].x * inv), __float2half_rn(v[q].y * inv));
        *(uint32_t*)&g_kwH[(size_t)w * TT + e0 + 2] =
            pack2h(__float2half_rn(v[q].z * inv), __float2half_rn(v[q].w * inv));
    }
}

// fused emb prep: one warp per vocab row; read fp32 once,
// write normalized fp16 (embH) + raw fp16 (embR).
__global__ void emb_prep(const float* __restrict__ emb)
{
    const int w    = (blockIdx.x * blockDim.x + threadIdx.x) >> 5;
    const int lane = threadIdx.x & 31;
    if (w >= VV) return;
    const float4* row = (const float4*)(emb + (size_t)w * TT);
    float4 v[4];
    float ss = 0.f;
    #pragma unroll
    for (int q = 0; q < 4; q++) {
        v[q] = row[lane + 32 * q];
        ss += v[q].x * v[q].x + v[q].y * v[q].y + v[q].z * v[q].z + v[q].w * v[q].w;
    }
    #pragma unroll
    for (int o = 16; o > 0; o >>= 1) ss += __shfl_xor_sync(0xffffffffu, ss, o);
    const float inv = 1.f / fmaxf(sqrtf(ss), 1e-8f);
    #pragma unroll
    for (int q = 0; q < 4; q++) {
        const int e0 = (lane + 32 * q) * 4;
        *(uint32_t*)&g_embR[(size_t)w * TT + e0] =
            pack2h(__float2half_rn(v[q].x), __float2half_rn(v[q].y));
        *(uint32_t*)&g_embR[(size_t)w * TT + e0 + 2] =
            pack2h(__float2half_rn(v[q].z), __float2half_rn(v[q].w));
        *(uint32_t*)&g_embH[(size_t)w * TT + e0] =
            pack2h(__float2half_rn(v[q].x * inv), __float2half_rn(v[q].y * inv));
        *(uint32_t*)&g_embH[(size_t)w * TT + e0 + 2] =
            pack2h(__float2half_rn(v[q].z * inv), __float2half_rn(v[q].w * inv));
    }
}

// =============================================================================
extern "C" void kernel_launch(void* const* d_in, const int* in_sizes, int n_in,
                              void* d_out, int out_size)
{
    const float* audio = (const float*)d_in[0];
    const float* W     = (const float*)d_in[1];
    const float* bias  = (const float*)d_in[2];
    const float* emb   = (const float*)d_in[3];
    float* out = (float*)d_out;

    cudaFuncSetAttribute(mma_gemm<0>, cudaFuncAttributeMaxDynamicSharedMemorySize, SMEMSZ);
    cudaFuncSetAttribute(mma_gemm<1>, cudaFuncAttributeMaxDynamicSharedMemorySize, SMEMSZ);

    float *kw, *rowsum;
    cudaGetSymbolAddress((void**)&kw,     g_kw);
    cudaGetSymbolAddress((void**)&rowsum, g_rowsum);

    cudaMemsetAsync(kw,     0, (size_t)BN * TT * sizeof(float), 0);
    cudaMemsetAsync(rowsum, 0, BN * sizeof(float), 0);
    cudaMemsetAsync(out,    0, (size_t)out_size * sizeof(float), 0);

    proj_gemm<<<dim3(TT / 128, BN / 128, 4), 256>>>(audio, W, kw);
    kw_norm_pack<<<BN / 8, 256>>>(bias);
    emb_prep<<<VV / 8, 256>>>(emb);

    // GEMM1: logits + exp epilogue
    mma_gemm<0><<<dim3(BN / 128, VV / 128), 512, SMEMSZ>>>(nullptr);
    // GEMM2: x = n-tiles (4), y = m-tiles (8), z = split-K (9)
    mma_gemm<1><<<dim3(TT / 128, BN / 128, 9), 512, SMEMSZ>>>(out);
}

// round 9
// speedup vs baseline: 1.0421x; 1.0096x over previous
#include <cuda_runtime.h>
#include <cuda_fp16.h>
#include <cstdint>
#include <cstddef>

#define BN 1024
#define DD 768
#define TT 512
#define VV 49408

// ------------------------- static device workspace --------------------------
__device__ float g_kw[BN * TT];            // projected keywords fp32 (split-K accum)
__device__ float g_rowsum[BN];             // softmax denominators (scaled)
__device__ float g_norm[VV];               // ||emb_v|| (fp32)
__device__ __half g_kwH[BN * TT];                  // normalized kw, fp16
__device__ __half g_embH[(size_t)VV * TT];         // NORMALIZED emb [v][t], fp16
__device__ __half g_probs[(size_t)BN * VV];        // scaled probs * ||emb_v||, fp16

// ------------------------------ helpers -------------------------------------
__device__ __forceinline__ uint32_t smem_u32(const void* p) {
    uint32_t a;
    asm("{ .reg .u64 t; cvta.to.shared.u64 t, %1; cvt.u32.u64 %0, t; }"
        : "=r"(a) : "l"(p));
    return a;
}
__device__ __forceinline__ void cp16(uint32_t s, const void* g) {
    asm volatile("cp.async.cg.shared.global [%0], [%1], 16;" :: "r"(s), "l"(g));
}
__device__ __forceinline__ void ldsm4(uint32_t* r, uint32_t addr) {
    asm volatile("ldmatrix.sync.aligned.m8n8.x4.shared.b16 {%0,%1,%2,%3}, [%4];"
        : "=r"(r[0]), "=r"(r[1]), "=r"(r[2]), "=r"(r[3]) : "r"(addr));
}
__device__ __forceinline__ void ldsm4t(uint32_t* r, uint32_t addr) {
    asm volatile("ldmatrix.sync.aligned.m8n8.x4.trans.shared.b16 {%0,%1,%2,%3}, [%4];"
        : "=r"(r[0]), "=r"(r[1]), "=r"(r[2]), "=r"(r[3]) : "r"(addr));
}
__device__ __forceinline__ void mma16816(float* c, const uint32_t* a, const uint32_t* b) {
    asm volatile("mma.sync.aligned.m16n8k16.row.col.f32.f16.f16.f32 "
        "{%0,%1,%2,%3}, {%4,%5,%6,%7}, {%8,%9}, {%0,%1,%2,%3};"
        : "+f"(c[0]), "+f"(c[1]), "+f"(c[2]), "+f"(c[3])
        : "r"(a[0]), "r"(a[1]), "r"(a[2]), "r"(a[3]), "r"(b[0]), "r"(b[1]));
}
__device__ __forceinline__ uint32_t pack2h(float a, float b) {
    const __half2 h = __floats2half2_rn(a, b);
    return *reinterpret_cast<const uint32_t*>(&h);
}

// smem: A plane 128x144B; B plane: EPI0 128x144B, EPI1 64x272B (both <= 18432)
#define ROWA   144
#define ROWBT  272
#define PLANE  18432
#define STAGE  (2 * PLANE)            // 36864
#define NSTAGE 2
#define SMEMSZ (NSTAGE * STAGE + 512) // 74240 -> 2 CTAs/SM

#define PSCALE 16384.f

// =============================================================================
// fp16 warp-MMA GEMM, CTA tile 128x128, BK=64, 512 thr, 16 warps, warp 32x32.
// fp32 accumulate. 2-stage cp.async double buffer.
// EPI==0: logits -> exp -> probs * ||emb_v|| (fp16) + rowsum atomics
// EPI==1: VQ GEMM split-K vs NORMALIZED emb (ldmatrix.trans) -> atomicAdd out
// =============================================================================
template<int EPI>
__global__ __launch_bounds__(512, 2) void mma_gemm(float* __restrict__ outf)
{
    constexpr uint32_t LDA = (EPI == 0) ? TT : VV;   // A stride (elements)
    extern __shared__ char smem[];
    const uint32_t sbase = smem_u32(smem);
    const int tid = threadIdx.x;
    const int lane = tid & 31, wid = tid >> 5;      // wid 0..15
    const int warpM = wid & 3, warpN = wid >> 2;    // 4 x 4 warp grid, 32x32 tiles

    const __half *A, *B;
    int m0, n0, c0, c1;
    if (EPI == 0) {
        A = g_kwH; B = g_embH;
        m0 = blockIdx.x * 128; n0 = blockIdx.y * 128;
        c0 = 0; c1 = TT / 64;
    } else {
        A = g_probs; B = g_embH;
        n0 = blockIdx.x * 128; m0 = blockIdx.y * 128;
        const long tot = VV / 64;
        c0 = (int)((tot * blockIdx.z) / gridDim.z);
        c1 = (int)((tot * (blockIdx.z + 1)) / gridDim.z);
    }
    const int nch = c1 - c0;

    // per-CTA emb norms for the epilogue (EPI==0 only)
    float* sNorm = (float*)(smem + NSTAGE * STAGE);
    if (EPI == 0 && tid < 128) sNorm[tid] = g_norm[n0 + tid];

    // ---- loader thread geometry (512 threads, 32-bit offsets) ----
    const uint32_t ch   = tid & 7;           // 16B chunk within 64-elem row piece
    const uint32_t rowA = tid >> 3;          // 0..63, second half via +64
    uint32_t aOff = (uint32_t)(m0 + rowA) * LDA + (uint32_t)c0 * 64 + ch * 8;
    const uint32_t aSo = rowA * ROWA + ch * 16;
    uint32_t bOff, bSo;
    if (EPI == 0) {
        bOff = (uint32_t)(n0 + rowA) * TT + (uint32_t)c0 * 64 + ch * 8;
        bSo  = aSo;
    } else {
        const uint32_t rb = tid >> 4, cb = tid & 15;   // 64 rows x 256B, 2 passes of 32
        bOff = ((uint32_t)c0 * 64 + rb) * TT + (uint32_t)n0 + cb * 8;
        bSo  = rb * ROWBT + cb * 16;
    }

    auto issue = [&](uint32_t st) {
        #pragma unroll
        for (int p = 0; p < 2; p++) {
            cp16(st + aSo + p * (64 * ROWA), A + aOff + p * (64 * LDA));
            if (EPI == 0)
                cp16(st + PLANE + bSo + p * (64 * ROWA), B + bOff + p * (64 * TT));
            else
                cp16(st + PLANE + bSo + p * (32 * ROWBT), B + bOff + p * (32 * TT));
        }
        aOff += 64;
        bOff += (EPI == 0) ? 64 : 64 * TT;
    };

    // ---- compute fragment smem bases ----
    const uint32_t saOff = (uint32_t)(warpM * 32 + (lane & 15)) * ROWA + ((lane >> 4) << 4);
    uint32_t sbOff;
    if (EPI == 0)
        sbOff = PLANE + (uint32_t)(warpN * 32 + (lane & 15)) * ROWA + ((lane >> 4) << 4);
    else
        sbOff = PLANE + (uint32_t)((lane & 7) + ((lane >> 4) << 3)) * ROWBT
              + (uint32_t)(warpN * 32 + ((lane >> 3) & 1) * 8) * 2;

    float acc[2][4][4];
    #pragma unroll
    for (int i = 0; i < 2; i++)
        #pragma unroll
        for (int j = 0; j < 4; j++)
            #pragma unroll
            for (int k = 0; k < 4; k++) acc[i][j][k] = 0.f;

    // ---- prologue: 2 stages in flight ----
    issue(sbase);
    asm volatile("cp.async.commit_group;" ::: "memory");
    issue(sbase + STAGE);
    asm volatile("cp.async.commit_group;" ::: "memory");

    for (int c = 0; c < nch; c++) {
        asm volatile("cp.async.wait_group 1;" ::: "memory");
        __syncthreads();
        const uint32_t st = sbase + (uint32_t)(c & 1) * STAGE;

        #pragma unroll
        for (int ks = 0; ks < 4; ks++) {
            const uint32_t ko = ks * 32;
            uint32_t a[2][4], b[2][4];
            #pragma unroll
            for (int mf = 0; mf < 2; mf++)
                ldsm4(a[mf], st + saOff + mf * (16 * ROWA) + ko);
            if (EPI == 0) {
                #pragma unroll
                for (int g = 0; g < 2; g++)
                    ldsm4(b[g], st + sbOff + g * (16 * ROWA) + ko);
            } else {
                #pragma unroll
                for (int g = 0; g < 2; g++)
                    ldsm4t(b[g], st + sbOff + ks * (16 * ROWBT) + g * 32);
            }
            #pragma unroll
            for (int mf = 0; mf < 2; mf++)
                #pragma unroll
                for (int nf = 0; nf < 4; nf++) {
                    uint32_t bf[2] = { b[nf >> 1][nf & 1],
                                       b[nf >> 1][2 + (nf & 1)] };
                    mma16816(acc[mf][nf], a[mf], bf);
                }
        }
        __syncthreads();
        if (c + 2 < nch) issue(st);
        asm volatile("cp.async.commit_group;" ::: "memory");
    }

    if (EPI == 0) {
        #pragma unroll
        for (int mf = 0; mf < 2; mf++) {
            const int r0 = m0 + warpM * 32 + mf * 16 + (lane >> 2);
            float rs0 = 0.f, rs1 = 0.f;
            #pragma unroll
            for (int nf = 0; nf < 4; nf++) {
                const int cl = warpN * 32 + nf * 8 + (lane & 3) * 2;  // local col
                const int cb = n0 + cl;
                // p = exp(10*cos - 10) * PSCALE  (scale cancels in normalization)
                const float e0 = __expf(acc[mf][nf][0] * 10.f - 10.f) * PSCALE;
                const float e1 = __expf(acc[mf][nf][1] * 10.f - 10.f) * PSCALE;
                const float e2 = __expf(acc[mf][nf][2] * 10.f - 10.f) * PSCALE;
                const float e3 = __expf(acc[mf][nf][3] * 10.f - 10.f) * PSCALE;
                rs0 += e0 + e1;  rs1 += e2 + e3;
                // fold ||emb_v|| into stored probs (GEMM2 then uses normalized emb)
                const float w0 = sNorm[cl], w1 = sNorm[cl + 1];
                *(uint32_t*)&g_probs[(size_t)r0 * VV + cb] = pack2h(e0 * w0, e1 * w1);
                *(uint32_t*)&g_probs[(size_t)(r0 + 8) * VV + cb] = pack2h(e2 * w0, e3 * w1);
            }
            rs0 += __shfl_xor_sync(0xffffffffu, rs0, 1);
            rs0 += __shfl_xor_sync(0xffffffffu, rs0, 2);
            rs1 += __shfl_xor_sync(0xffffffffu, rs1, 1);
            rs1 += __shfl_xor_sync(0xffffffffu, rs1, 2);
            if ((lane & 3) == 0) {
                atomicAdd(&g_rowsum[r0],     rs0);
                atomicAdd(&g_rowsum[r0 + 8], rs1);
            }
        }
    } else {
        #pragma unroll
        for (int mf = 0; mf < 2; mf++) {
            const int r0 = m0 + warpM * 32 + mf * 16 + (lane >> 2);
            const float s0 = 1.f / g_rowsum[r0];
            const float s1 = 1.f / g_rowsum[r0 + 8];
            #pragma unroll
            for (int nf = 0; nf < 4; nf++) {
                const int cb = n0 + warpN * 32 + nf * 8 + (lane & 3) * 2;
                atomicAdd(&outf[(size_t)r0 * TT + cb],           acc[mf][nf][0] * s0);
                atomicAdd(&outf[(size_t)r0 * TT + cb + 1],       acc[mf][nf][1] * s0);
                atomicAdd(&outf[(size_t)(r0 + 8) * TT + cb],     acc[mf][nf][2] * s1);
                atomicAdd(&outf[(size_t)(r0 + 8) * TT + cb + 1], acc[mf][nf][3] * s1);
            }
        }
    }
}

// =============================================================================
// fp32 SIMT projection GEMM, split-K z=4 (128 CTAs): kw += audio @ W
// =============================================================================
__global__ __launch_bounds__(256, 2)
void proj_gemm(const float* __restrict__ A, const float* __restrict__ B,
               float* __restrict__ C)
{
    __shared__ float As[16][132];
    __shared__ float Bs[16][132];
    const int tid = threadIdx.x;
    const int m0 = blockIdx.y * 128, n0 = blockIdx.x * 128;
    const int kb = blockIdx.z * (DD / 4), ke = kb + DD / 4;
    const int tx = tid & 15, ty = tid >> 4;
    const int a_row = tid >> 2, a_c4 = (tid & 3) * 4;
    const int b_k = tid >> 5, b_n4 = (tid & 31) * 4;

    float acc[8][8];
    #pragma unroll
    for (int i = 0; i < 8; i++)
        #pragma unroll
        for (int j = 0; j < 8; j++) acc[i][j] = 0.f;

    for (int k0 = kb; k0 < ke; k0 += 16) {
        float4 va0 = *(const float4*)&A[(size_t)(m0 + a_row)      * DD + k0 + a_c4];
        float4 va1 = *(const float4*)&A[(size_t)(m0 + a_row + 64) * DD + k0 + a_c4];
        As[a_c4 + 0][a_row] = va0.x;  As[a_c4 + 1][a_row] = va0.y;
        As[a_c4 + 2][a_row] = va0.z;  As[a_c4 + 3][a_row] = va0.w;
        As[a_c4 + 0][a_row + 64] = va1.x;  As[a_c4 + 1][a_row + 64] = va1.y;
        As[a_c4 + 2][a_row + 64] = va1.z;  As[a_c4 + 3][a_row + 64] = va1.w;
        *(float4*)&Bs[b_k][b_n4]     = *(const float4*)&B[(size_t)(k0 + b_k)     * TT + n0 + b_n4];
        *(float4*)&Bs[b_k + 8][b_n4] = *(const float4*)&B[(size_t)(k0 + b_k + 8) * TT + n0 + b_n4];
        __syncthreads();
        #pragma unroll
        for (int kk = 0; kk < 16; kk++) {
            float a[8], b[8];
            *(float4*)&a[0] = *(const float4*)&As[kk][ty * 8];
            *(float4*)&a[4] = *(const float4*)&As[kk][ty * 8 + 4];
            *(float4*)&b[0] = *(const float4*)&Bs[kk][tx * 8];
            *(float4*)&b[4] = *(const float4*)&Bs[kk][tx * 8 + 4];
            #pragma unroll
            for (int i = 0; i < 8; i++)
                #pragma unroll
                for (int j = 0; j < 8; j++)
                    acc[i][j] = fmaf(a[i], b[j], acc[i][j]);
        }
        __syncthreads();
    }
    #pragma unroll
    for (int i = 0; i < 8; i++) {
        const int m = m0 + ty * 8 + i;
        #pragma unroll
        for (int j = 0; j < 8; j++)
            atomicAdd(&C[(size_t)m * TT + n0 + tx * 8 + j], acc[i][j]);
    }
}

// kw rows: add bias, L2-normalize, write fp16
__global__ void kw_norm_pack(const float* __restrict__ bias)
{
    const int w    = (blockIdx.x * blockDim.x + threadIdx.x) >> 5;
    const int lane = threadIdx.x & 31;
    if (w >= BN) return;
    const float4* row = (const float4*)(g_kw + (size_t)w * TT);
    const float4* b4  = (const float4*)bias;
    float4 v[4];
    float ss = 0.f;
    #pragma unroll
    for (int q = 0; q < 4; q++) {
        v[q] = row[lane + 32 * q];
        const float4 bb = b4[lane + 32 * q];
        v[q].x += bb.x; v[q].y += bb.y; v[q].z += bb.z; v[q].w += bb.w;
        ss += v[q].x * v[q].x + v[q].y * v[q].y + v[q].z * v[q].z + v[q].w * v[q].w;
    }
    #pragma unroll
    for (int o = 16; o > 0; o >>= 1) ss += __shfl_xor_sync(0xffffffffu, ss, o);
    const float inv = 1.f / fmaxf(sqrtf(ss), 1e-8f);
    #pragma unroll
    for (int q = 0; q < 4; q++) {
        const int e0 = (lane + 32 * q) * 4;
        const uint2 pk = make_uint2(pack2h(v[q].x * inv, v[q].y * inv),
                                    pack2h(v[q].z * inv, v[q].w * inv));
        *(uint2*)&g_kwH[(size_t)w * TT + e0] = pk;
    }
}

// emb prep: one warp per vocab row; read fp32 once,
// write normalized fp16 (embH) + row norm (g_norm).
__global__ __launch_bounds__(512)
void emb_prep(const float* __restrict__ emb)
{
    const int w    = (blockIdx.x * blockDim.x + threadIdx.x) >> 5;
    const int lane = threadIdx.x & 31;
    if (w >= VV) return;
    const float4* row = (const float4*)(emb + (size_t)w * TT);
    float4 v[4];
    float ss = 0.f;
    #pragma unroll
    for (int q = 0; q < 4; q++) {
        v[q] = row[lane + 32 * q];
        ss += v[q].x * v[q].x + v[q].y * v[q].y + v[q].z * v[q].z + v[q].w * v[q].w;
    }
    #pragma unroll
    for (int o = 16; o > 0; o >>= 1) ss += __shfl_xor_sync(0xffffffffu, ss, o);
    const float nrm = sqrtf(ss);
    const float inv = 1.f / fmaxf(nrm, 1e-8f);
    if (lane == 0) g_norm[w] = nrm;
    #pragma unroll
    for (int q = 0; q < 4; q++) {
        const int e0 = (lane + 32 * q) * 4;
        const uint2 pk = make_uint2(pack2h(v[q].x * inv, v[q].y * inv),
                                    pack2h(v[q].z * inv, v[q].w * inv));
        *(uint2*)&g_embH[(size_t)w * TT + e0] = pk;
    }
}

// =============================================================================
extern "C" void kernel_launch(void* const* d_in, const int* in_sizes, int n_in,
                              void* d_out, int out_size)
{
    const float* audio = (const float*)d_in[0];
    const float* W     = (const float*)d_in[1];
    const float* bias  = (const float*)d_in[2];
    const float* emb   = (const float*)d_in[3];
    float* out = (float*)d_out;

    cudaFuncSetAttribute(mma_gemm<0>, cudaFuncAttributeMaxDynamicSharedMemorySize, SMEMSZ);
    cudaFuncSetAttribute(mma_gemm<1>, cudaFuncAttributeMaxDynamicSharedMemorySize, SMEMSZ);

    float *kw, *rowsum;
    cudaGetSymbolAddress((void**)&kw,     g_kw);
    cudaGetSymbolAddress((void**)&rowsum, g_rowsum);

    cudaMemsetAsync(kw,     0, (size_t)BN * TT * sizeof(float), 0);
    cudaMemsetAsync(rowsum, 0, BN * sizeof(float), 0);
    cudaMemsetAsync(out,    0, (size_t)out_size * sizeof(float), 0);

    proj_gemm<<<dim3(TT / 128, BN / 128, 4), 256>>>(audio, W, kw);
    kw_norm_pack<<<BN / 8, 256>>>(bias);
    emb_prep<<<VV / 16, 512>>>(emb);

    // GEMM1: logits + exp epilogue
    mma_gemm<0><<<dim3(BN / 128, VV / 128), 512, SMEMSZ>>>(nullptr);
    // GEMM2: x = n-tiles (4), y = m-tiles (8), z = split-K (9)
    mma_gemm<1><<<dim3(TT / 128, BN / 128, 9), 512, SMEMSZ>>>(out);
}

// round 10
// speedup vs baseline: 1.1049x; 1.0603x over previous
#include <cuda_runtime.h>
#include <cuda_fp16.h>
#include <cstdint>
#include <cstddef>

#define BN 1024
#define DD 768
#define TT 512
#define VV 49408

// ------------------------- static device workspace --------------------------
__device__ float g_kw[BN * TT];            // projected keywords fp32 (split-K accum)
__device__ float g_rowsum[BN];             // softmax denominators (scaled)
__device__ float g_norm[VV];               // ||emb_v|| (fp32)
__device__ __half g_kwH[BN * TT];                  // normalized kw, fp16
__device__ __half g_audioH[BN * DD];               // audio fp16
__device__ __half g_WH[DD * TT];                   // W_proj fp16 [k][n]
__device__ __half g_embH[(size_t)VV * TT];         // NORMALIZED emb [v][t], fp16
__device__ __half g_probs[(size_t)BN * VV];        // scaled probs * ||emb_v||, fp16

// ------------------------------ helpers -------------------------------------
__device__ __forceinline__ uint32_t smem_u32(const void* p) {
    uint32_t a;
    asm("{ .reg .u64 t; cvta.to.shared.u64 t, %1; cvt.u32.u64 %0, t; }"
        : "=r"(a) : "l"(p));
    return a;
}
__device__ __forceinline__ void cp16(uint32_t s, const void* g) {
    asm volatile("cp.async.cg.shared.global [%0], [%1], 16;" :: "r"(s), "l"(g));
}
__device__ __forceinline__ void ldsm4(uint32_t* r, uint32_t addr) {
    asm volatile("ldmatrix.sync.aligned.m8n8.x4.shared.b16 {%0,%1,%2,%3}, [%4];"
        : "=r"(r[0]), "=r"(r[1]), "=r"(r[2]), "=r"(r[3]) : "r"(addr));
}
__device__ __forceinline__ void ldsm4t(uint32_t* r, uint32_t addr) {
    asm volatile("ldmatrix.sync.aligned.m8n8.x4.trans.shared.b16 {%0,%1,%2,%3}, [%4];"
        : "=r"(r[0]), "=r"(r[1]), "=r"(r[2]), "=r"(r[3]) : "r"(addr));
}
__device__ __forceinline__ void mma16816(float* c, const uint32_t* a, const uint32_t* b) {
    asm volatile("mma.sync.aligned.m16n8k16.row.col.f32.f16.f16.f32 "
        "{%0,%1,%2,%3}, {%4,%5,%6,%7}, {%8,%9}, {%0,%1,%2,%3};"
        : "+f"(c[0]), "+f"(c[1]), "+f"(c[2]), "+f"(c[3])
        : "r"(a[0]), "r"(a[1]), "r"(a[2]), "r"(a[3]), "r"(b[0]), "r"(b[1]));
}
__device__ __forceinline__ uint32_t pack2h(float a, float b) {
    const __half2 h = __floats2half2_rn(a, b);
    return *reinterpret_cast<const uint32_t*>(&h);
}

// smem: A plane 128x144B; B plane: direct 128x144B, trans 64x272B (<= 18432)
#define ROWA   144
#define ROWBT  272
#define PLANE  18432
#define STAGE  (2 * PLANE)            // 36864
#define NSTAGE 2
#define SMEMSZ (NSTAGE * STAGE + 512) // 74240 -> 2 CTAs/SM

#define PSCALE 16384.f

// =============================================================================
// fp16 warp-MMA GEMM, CTA tile 128x128, BK=64, 512 thr, 16 warps, warp 32x32.
// fp32 accumulate. 2-stage cp.async double buffer.
// EPI==0: logits (A=kwH, B=embH direct) -> exp -> probs*||emb|| + rowsum atomics
// EPI==1: VQ GEMM split-K (A=probs, B=embH trans) -> (1/rowsum)*atomicAdd out
// EPI==2: projection split-K (A=audioH, B=WH trans) -> atomicAdd into g_kw
// =============================================================================
template<int EPI>
__global__ __launch_bounds__(512, 2) void mma_gemm(float* __restrict__ outf)
{
    constexpr uint32_t LDA  = (EPI == 0) ? TT : (EPI == 1) ? VV : DD;
    constexpr uint32_t LDB  = TT;                    // emb / W row stride
    constexpr int      NCHT = (EPI == 0) ? TT / 64 : (EPI == 1) ? VV / 64 : DD / 64;
    extern __shared__ char smem[];
    const uint32_t sbase = smem_u32(smem);
    const int tid = threadIdx.x;
    const int lane = tid & 31, wid = tid >> 5;      // wid 0..15
    const int warpM = wid & 3, warpN = wid >> 2;    // 4 x 4 warp grid, 32x32 tiles

    const __half *A, *B;
    int m0, n0, c0, c1;
    if (EPI == 0) {
        A = g_kwH; B = g_embH;
        m0 = blockIdx.x * 128; n0 = blockIdx.y * 128;
        c0 = 0; c1 = NCHT;
    } else {
        A = (EPI == 1) ? g_probs : g_audioH;
        B = (EPI == 1) ? g_embH  : g_WH;
        n0 = blockIdx.x * 128; m0 = blockIdx.y * 128;
        c0 = (int)(((long)NCHT * blockIdx.z) / gridDim.z);
        c1 = (int)(((long)NCHT * (blockIdx.z + 1)) / gridDim.z);
    }
    const int nch = c1 - c0;

    // per-CTA emb norms for the epilogue (EPI==0 only)
    float* sNorm = (float*)(smem + NSTAGE * STAGE);
    if (EPI == 0 && tid < 128) sNorm[tid] = g_norm[n0 + tid];

    // ---- loader thread geometry (512 threads, 32-bit offsets) ----
    const uint32_t ch   = tid & 7;           // 16B chunk within 64-elem row piece
    const uint32_t rowA = tid >> 3;          // 0..63, second half via +64
    uint32_t aOff = (uint32_t)(m0 + rowA) * LDA + (uint32_t)c0 * 64 + ch * 8;
    const uint32_t aSo = rowA * ROWA + ch * 16;
    uint32_t bOff, bSo;
    if (EPI == 0) {
        bOff = (uint32_t)(n0 + rowA) * LDB + (uint32_t)c0 * 64 + ch * 8;
        bSo  = aSo;
    } else {
        const uint32_t rb = tid >> 4, cb = tid & 15;   // 64 rows x 256B, 2 passes of 32
        bOff = ((uint32_t)c0 * 64 + rb) * LDB + (uint32_t)n0 + cb * 8;
        bSo  = rb * ROWBT + cb * 16;
    }

    auto issue = [&](uint32_t st) {
        #pragma unroll
        for (int p = 0; p < 2; p++) {
            cp16(st + aSo + p * (64 * ROWA), A + aOff + p * (64 * LDA));
            if (EPI == 0)
                cp16(st + PLANE + bSo + p * (64 * ROWA), B + bOff + p * (64 * LDB));
            else
                cp16(st + PLANE + bSo + p * (32 * ROWBT), B + bOff + p * (32 * LDB));
        }
        aOff += 64;
        bOff += (EPI == 0) ? 64 : 64 * LDB;
    };

    // ---- compute fragment smem bases ----
    const uint32_t saOff = (uint32_t)(warpM * 32 + (lane & 15)) * ROWA + ((lane >> 4) << 4);
    uint32_t sbOff;
    if (EPI == 0)
        sbOff = PLANE + (uint32_t)(warpN * 32 + (lane & 15)) * ROWA + ((lane >> 4) << 4);
    else
        sbOff = PLANE + (uint32_t)((lane & 7) + ((lane >> 4) << 3)) * ROWBT
              + (uint32_t)(warpN * 32 + ((lane >> 3) & 1) * 8) * 2;

    float acc[2][4][4];
    #pragma unroll
    for (int i = 0; i < 2; i++)
        #pragma unroll
        for (int j = 0; j < 4; j++)
            #pragma unroll
            for (int k = 0; k < 4; k++) acc[i][j][k] = 0.f;

    // ---- prologue: 2 stages in flight ----
    issue(sbase);
    asm volatile("cp.async.commit_group;" ::: "memory");
    issue(sbase + STAGE);
    asm volatile("cp.async.commit_group;" ::: "memory");

    for (int c = 0; c < nch; c++) {
        asm volatile("cp.async.wait_group 1;" ::: "memory");
        __syncthreads();
        const uint32_t st = sbase + (uint32_t)(c & 1) * STAGE;

        #pragma unroll
        for (int ks = 0; ks < 4; ks++) {
            const uint32_t ko = ks * 32;
            uint32_t a[2][4], b[2][4];
            #pragma unroll
            for (int mf = 0; mf < 2; mf++)
                ldsm4(a[mf], st + saOff + mf * (16 * ROWA) + ko);
            if (EPI == 0) {
                #pragma unroll
                for (int g = 0; g < 2; g++)
                    ldsm4(b[g], st + sbOff + g * (16 * ROWA) + ko);
            } else {
                #pragma unroll
                for (int g = 0; g < 2; g++)
                    ldsm4t(b[g], st + sbOff + ks * (16 * ROWBT) + g * 32);
            }
            #pragma unroll
            for (int mf = 0; mf < 2; mf++)
                #pragma unroll
                for (int nf = 0; nf < 4; nf++) {
                    uint32_t bf[2] = { b[nf >> 1][nf & 1],
                                       b[nf >> 1][2 + (nf & 1)] };
                    mma16816(acc[mf][nf], a[mf], bf);
                }
        }
        __syncthreads();
        if (c + 2 < nch) issue(st);
        asm volatile("cp.async.commit_group;" ::: "memory");
    }

    if (EPI == 0) {
        #pragma unroll
        for (int mf = 0; mf < 2; mf++) {
            const int r0 = m0 + warpM * 32 + mf * 16 + (lane >> 2);
            float rs0 = 0.f, rs1 = 0.f;
            #pragma unroll
            for (int nf = 0; nf < 4; nf++) {
                const int cl = warpN * 32 + nf * 8 + (lane & 3) * 2;  // local col
                const int cb = n0 + cl;
                // p = exp(10*cos - 10) * PSCALE  (scale cancels in normalization)
                const float e0 = __expf(acc[mf][nf][0] * 10.f - 10.f) * PSCALE;
                const float e1 = __expf(acc[mf][nf][1] * 10.f - 10.f) * PSCALE;
                const float e2 = __expf(acc[mf][nf][2] * 10.f - 10.f) * PSCALE;
                const float e3 = __expf(acc[mf][nf][3] * 10.f - 10.f) * PSCALE;
                rs0 += e0 + e1;  rs1 += e2 + e3;
                // fold ||emb_v|| into stored probs (GEMM2 uses normalized emb)
                const float w0 = sNorm[cl], w1 = sNorm[cl + 1];
                *(uint32_t*)&g_probs[(size_t)r0 * VV + cb] = pack2h(e0 * w0, e1 * w1);
                *(uint32_t*)&g_probs[(size_t)(r0 + 8) * VV + cb] = pack2h(e2 * w0, e3 * w1);
            }
            rs0 += __shfl_xor_sync(0xffffffffu, rs0, 1);
            rs0 += __shfl_xor_sync(0xffffffffu, rs0, 2);
            rs1 += __shfl_xor_sync(0xffffffffu, rs1, 1);
            rs1 += __shfl_xor_sync(0xffffffffu, rs1, 2);
            if ((lane & 3) == 0) {
                atomicAdd(&g_rowsum[r0],     rs0);
                atomicAdd(&g_rowsum[r0 + 8], rs1);
            }
        }
    } else {
        #pragma unroll
        for (int mf = 0; mf < 2; mf++) {
            const int r0 = m0 + warpM * 32 + mf * 16 + (lane >> 2);
            const float s0 = (EPI == 1) ? 1.f / g_rowsum[r0]     : 1.f;
            const float s1 = (EPI == 1) ? 1.f / g_rowsum[r0 + 8] : 1.f;
            #pragma unroll
            for (int nf = 0; nf < 4; nf++) {
                const int cb = n0 + warpN * 32 + nf * 8 + (lane & 3) * 2;
                atomicAdd(&outf[(size_t)r0 * TT + cb],           acc[mf][nf][0] * s0);
                atomicAdd(&outf[(size_t)r0 * TT + cb + 1],       acc[mf][nf][1] * s0);
                atomicAdd(&outf[(size_t)(r0 + 8) * TT + cb],     acc[mf][nf][2] * s1);
                atomicAdd(&outf[(size_t)(r0 + 8) * TT + cb + 1], acc[mf][nf][3] * s1);
            }
        }
    }
}

// fp32 -> fp16 streaming pack (vectorized, grid-stride)
__global__ __launch_bounds__(512)
void pack_f16(const float* __restrict__ src, __half* __restrict__ dst, int n4)
{
    for (int i = blockIdx.x * blockDim.x + threadIdx.x; i < n4;
         i += gridDim.x * blockDim.x) {
        const float4 v = ((const float4*)src)[i];
        const uint2 pk = make_uint2(pack2h(v.x, v.y), pack2h(v.z, v.w));
        ((uint2*)dst)[i] = pk;
    }
}

// kw rows: add bias, L2-normalize, write fp16
__global__ void kw_norm_pack(const float* __restrict__ bias)
{
    const int w    = (blockIdx.x * blockDim.x + threadIdx.x) >> 5;
    const int lane = threadIdx.x & 31;
    if (w >= BN) return;
    const float4* row = (const float4*)(g_kw + (size_t)w * TT);
    const float4* b4  = (const float4*)bias;
    float4 v[4];
    float ss = 0.f;
    #pragma unroll
    for (int q = 0; q < 4; q++) {
        v[q] = row[lane + 32 * q];
        const float4 bb = b4[lane + 32 * q];
        v[q].x += bb.x; v[q].y += bb.y; v[q].z += bb.z; v[q].w += bb.w;
        ss += v[q].x * v[q].x + v[q].y * v[q].y + v[q].z * v[q].z + v[q].w * v[q].w;
    }
    #pragma unroll
    for (int o = 16; o > 0; o >>= 1) ss += __shfl_xor_sync(0xffffffffu, ss, o);
    const float inv = 1.f / fmaxf(sqrtf(ss), 1e-8f);
    #pragma unroll
    for (int q = 0; q < 4; q++) {
        const int e0 = (lane + 32 * q) * 4;
        const uint2 pk = make_uint2(pack2h(v[q].x * inv, v[q].y * inv),
                                    pack2h(v[q].z * inv, v[q].w * inv));
        *(uint2*)&g_kwH[(size_t)w * TT + e0] = pk;
    }
}

// emb prep: one warp per vocab row; read fp32 once,
// write normalized fp16 (embH) + row norm (g_norm).
__global__ __launch_bounds__(512)
void emb_prep(const float* __restrict__ emb)
{
    const int w    = (blockIdx.x * blockDim.x + threadIdx.x) >> 5;
    const int lane = threadIdx.x & 31;
    if (w >= VV) return;
    const float4* row = (const float4*)(emb + (size_t)w * TT);
    float4 v[4];
    float ss = 0.f;
    #pragma unroll
    for (int q = 0; q < 4; q++) {
        v[q] = row[lane + 32 * q];
        ss += v[q].x * v[q].x + v[q].y * v[q].y + v[q].z * v[q].z + v[q].w * v[q].w;
    }
    #pragma unroll
    for (int o = 16; o > 0; o >>= 1) ss += __shfl_xor_sync(0xffffffffu, ss, o);
    const float nrm = sqrtf(ss);
    const float inv = 1.f / fmaxf(nrm, 1e-8f);
    if (lane == 0) g_norm[w] = nrm;
    #pragma unroll
    for (int q = 0; q < 4; q++) {
        const int e0 = (lane + 32 * q) * 4;
        const uint2 pk = make_uint2(pack2h(v[q].x * inv, v[q].y * inv),
                                    pack2h(v[q].z * inv, v[q].w * inv));
        *(uint2*)&g_embH[(size_t)w * TT + e0] = pk;
    }
}

// =============================================================================
extern "C" void kernel_launch(void* const* d_in, const int* in_sizes, int n_in,
                              void* d_out, int out_size)
{
    const float* audio = (const float*)d_in[0];
    const float* W     = (const float*)d_in[1];
    const float* bias  = (const float*)d_in[2];
    const float* emb   = (const float*)d_in[3];
    float* out = (float*)d_out;

    cudaFuncSetAttribute(mma_gemm<0>, cudaFuncAttributeMaxDynamicSharedMemorySize, SMEMSZ);
    cudaFuncSetAttribute(mma_gemm<1>, cudaFuncAttributeMaxDynamicSharedMemorySize, SMEMSZ);
    cudaFuncSetAttribute(mma_gemm<2>, cudaFuncAttributeMaxDynamicSharedMemorySize, SMEMSZ);

    float *kw, *rowsum;
    __half *audioH, *WH;
    cudaGetSymbolAddress((void**)&kw,     g_kw);
    cudaGetSymbolAddress((void**)&rowsum, g_rowsum);
    cudaGetSymbolAddress((void**)&audioH, g_audioH);
    cudaGetSymbolAddress((void**)&WH,     g_WH);

    cudaMemsetAsync(kw,     0, (size_t)BN * TT * sizeof(float), 0);
    cudaMemsetAsync(rowsum, 0, BN * sizeof(float), 0);
    cudaMemsetAsync(out,    0, (size_t)out_size * sizeof(float), 0);

    pack_f16<<<256, 512>>>(audio, audioH, BN * DD / 4);
    pack_f16<<<128, 512>>>(W,     WH,     DD * TT / 4);
    emb_prep<<<VV / 16, 512>>>(emb);

    // projection on tensor path: x = n-tiles (4), y = m-tiles (8), z = split-K (4)
    mma_gemm<2><<<dim3(TT / 128, BN / 128, 4), 512, SMEMSZ>>>(kw);
    kw_norm_pack<<<BN / 8, 256>>>(bias);

    // GEMM1: logits + exp epilogue
    mma_gemm<0><<<dim3(BN / 128, VV / 128), 512, SMEMSZ>>>(nullptr);
    // GEMM2: x = n-tiles (4), y = m-tiles (8), z = split-K (9)
    mma_gemm<1><<<dim3(TT / 128, BN / 128, 9), 512, SMEMSZ>>>(out);
}

// round 11
// speedup vs baseline: 1.1182x; 1.0121x over previous
#include <cuda_runtime.h>
#include <cuda_fp16.h>
#include <cstdint>
#include <cstddef>

#define BN 1024
#define DD 768
#define TT 512
#define VV 49408

// ------------------------- static device workspace --------------------------
__device__ float g_kw[BN * TT];            // projected keywords fp32 (split-K accum)
__device__ float g_rowsum[BN];             // softmax denominators (scaled)
__device__ float g_norm[VV];               // ||emb_v|| (fp32)
__device__ __half g_kwH[BN * TT];                  // normalized kw, fp16
__device__ __half g_audioH[BN * DD];               // audio fp16
__device__ __half g_WH[DD * TT];                   // W_proj fp16 [k][n]
__device__ __half g_embH[(size_t)VV * TT];         // NORMALIZED emb [v][t], fp16
__device__ __half g_probs[(size_t)BN * VV];        // scaled probs * ||emb_v||, fp16

// ------------------------------ helpers -------------------------------------
__device__ __forceinline__ uint32_t smem_u32(const void* p) {
    uint32_t a;
    asm("{ .reg .u64 t; cvta.to.shared.u64 t, %1; cvt.u32.u64 %0, t; }"
        : "=r"(a) : "l"(p));
    return a;
}
__device__ __forceinline__ void cp16(uint32_t s, const void* g) {
    asm volatile("cp.async.cg.shared.global [%0], [%1], 16;" :: "r"(s), "l"(g));
}
__device__ __forceinline__ void ldsm4(uint32_t* r, uint32_t addr) {
    asm volatile("ldmatrix.sync.aligned.m8n8.x4.shared.b16 {%0,%1,%2,%3}, [%4];"
        : "=r"(r[0]), "=r"(r[1]), "=r"(r[2]), "=r"(r[3]) : "r"(addr));
}
__device__ __forceinline__ void ldsm4t(uint32_t* r, uint32_t addr) {
    asm volatile("ldmatrix.sync.aligned.m8n8.x4.trans.shared.b16 {%0,%1,%2,%3}, [%4];"
        : "=r"(r[0]), "=r"(r[1]), "=r"(r[2]), "=r"(r[3]) : "r"(addr));
}
__device__ __forceinline__ void mma16816(float* c, const uint32_t* a, const uint32_t* b) {
    asm volatile("mma.sync.aligned.m16n8k16.row.col.f32.f16.f16.f32 "
        "{%0,%1,%2,%3}, {%4,%5,%6,%7}, {%8,%9}, {%0,%1,%2,%3};"
        : "+f"(c[0]), "+f"(c[1]), "+f"(c[2]), "+f"(c[3])
        : "r"(a[0]), "r"(a[1]), "r"(a[2]), "r"(a[3]), "r"(b[0]), "r"(b[1]));
}
__device__ __forceinline__ uint32_t pack2h(float a, float b) {
    const __half2 h = __floats2half2_rn(a, b);
    return *reinterpret_cast<const uint32_t*>(&h);
}

// smem: A plane 128x144B; B plane: direct 128x144B, trans 64x272B (<= 18432)
#define ROWA   144
#define ROWBT  272
#define PLANE  18432
#define STAGE  (2 * PLANE)            // 36864
#define NSTAGE 2
#define SMEMSZ (NSTAGE * STAGE + 512) // 74240 -> 2 CTAs/SM

#define PSCALE 16384.f

// =============================================================================
// fp16 warp-MMA GEMM, CTA tile 128x128, BK=64, 512 thr, 16 warps, warp 32x32.
// fp32 accumulate. 2-stage cp.async double buffer.
// EPI==0: logits (A=kwH, B=embH direct) -> exp -> probs*||emb|| + rowsum atomics
// EPI==1: VQ GEMM split-K (A=probs, B=embH trans) -> (1/rowsum)*atomicAdd out
// EPI==2: projection split-K (A=audioH, B=WH trans) -> atomicAdd into g_kw
// =============================================================================
template<int EPI>
__global__ __launch_bounds__(512, 2) void mma_gemm(float* __restrict__ outf)
{
    constexpr uint32_t LDA  = (EPI == 0) ? TT : (EPI == 1) ? VV : DD;
    constexpr uint32_t LDB  = TT;                    // emb / W row stride
    constexpr int      NCHT = (EPI == 0) ? TT / 64 : (EPI == 1) ? VV / 64 : DD / 64;
    extern __shared__ char smem[];
    const uint32_t sbase = smem_u32(smem);
    const int tid = threadIdx.x;
    const int lane = tid & 31, wid = tid >> 5;      // wid 0..15
    const int warpM = wid & 3, warpN = wid >> 2;    // 4 x 4 warp grid, 32x32 tiles

    const __half *A, *B;
    int m0, n0, c0, c1;
    if (EPI == 0) {
        A = g_kwH; B = g_embH;
        m0 = blockIdx.x * 128; n0 = blockIdx.y * 128;
        c0 = 0; c1 = NCHT;
    } else {
        A = (EPI == 1) ? g_probs : g_audioH;
        B = (EPI == 1) ? g_embH  : g_WH;
        n0 = blockIdx.x * 128; m0 = blockIdx.y * 128;
        c0 = (int)(((long)NCHT * blockIdx.z) / gridDim.z);
        c1 = (int)(((long)NCHT * (blockIdx.z + 1)) / gridDim.z);
    }
    const int nch = c1 - c0;

    // per-CTA emb norms for the epilogue (EPI==0 only)
    float* sNorm = (float*)(smem + NSTAGE * STAGE);
    if (EPI == 0 && tid < 128) sNorm[tid] = g_norm[n0 + tid];

    // ---- loader thread geometry (512 threads, 32-bit offsets) ----
    const uint32_t ch   = tid & 7;           // 16B chunk within 64-elem row piece
    const uint32_t rowA = tid >> 3;          // 0..63, second half via +64
    uint32_t aOff = (uint32_t)(m0 + rowA) * LDA + (uint32_t)c0 * 64 + ch * 8;
    const uint32_t aSo = rowA * ROWA + ch * 16;
    uint32_t bOff, bSo;
    if (EPI == 0) {
        bOff = (uint32_t)(n0 + rowA) * LDB + (uint32_t)c0 * 64 + ch * 8;
        bSo  = aSo;
    } else {
        const uint32_t rb = tid >> 4, cb = tid & 15;   // 64 rows x 256B, 2 passes of 32
        bOff = ((uint32_t)c0 * 64 + rb) * LDB + (uint32_t)n0 + cb * 8;
        bSo  = rb * ROWBT + cb * 16;
    }

    auto issue = [&](uint32_t st) {
        #pragma unroll
        for (int p = 0; p < 2; p++) {
            cp16(st + aSo + p * (64 * ROWA), A + aOff + p * (64 * LDA));
            if (EPI == 0)
                cp16(st + PLANE + bSo + p * (64 * ROWA), B + bOff + p * (64 * LDB));
            else
                cp16(st + PLANE + bSo + p * (32 * ROWBT), B + bOff + p * (32 * LDB));
        }
        aOff += 64;
        bOff += (EPI == 0) ? 64 : 64 * LDB;
    };

    // ---- compute fragment smem bases ----
    const uint32_t saOff = (uint32_t)(warpM * 32 + (lane & 15)) * ROWA + ((lane >> 4) << 4);
    uint32_t sbOff;
    if (EPI == 0)
        sbOff = PLANE + (uint32_t)(warpN * 32 + (lane & 15)) * ROWA + ((lane >> 4) << 4);
    else
        sbOff = PLANE + (uint32_t)((lane & 7) + ((lane >> 4) << 3)) * ROWBT
              + (uint32_t)(warpN * 32 + ((lane >> 3) & 1) * 8) * 2;

    float acc[2][4][4];
    #pragma unroll
    for (int i = 0; i < 2; i++)
        #pragma unroll
        for (int j = 0; j < 4; j++)
            #pragma unroll
            for (int k = 0; k < 4; k++) acc[i][j][k] = 0.f;

    // ---- prologue: 2 stages in flight ----
    issue(sbase);
    asm volatile("cp.async.commit_group;" ::: "memory");
    issue(sbase + STAGE);
    asm volatile("cp.async.commit_group;" ::: "memory");

    for (int c = 0; c < nch; c++) {
        asm volatile("cp.async.wait_group 1;" ::: "memory");
        __syncthreads();
        const uint32_t st = sbase + (uint32_t)(c & 1) * STAGE;

        #pragma unroll
        for (int ks = 0; ks < 4; ks++) {
            const uint32_t ko = ks * 32;
            uint32_t a[2][4], b[2][4];
            #pragma unroll
            for (int mf = 0; mf < 2; mf++)
                ldsm4(a[mf], st + saOff + mf * (16 * ROWA) + ko);
            if (EPI == 0) {
                #pragma unroll
                for (int g = 0; g < 2; g++)
                    ldsm4(b[g], st + sbOff + g * (16 * ROWA) + ko);
            } else {
                #pragma unroll
                for (int g = 0; g < 2; g++)
                    ldsm4t(b[g], st + sbOff + ks * (16 * ROWBT) + g * 32);
            }
            #pragma unroll
            for (int mf = 0; mf < 2; mf++)
                #pragma unroll
                for (int nf = 0; nf < 4; nf++) {
                    uint32_t bf[2] = { b[nf >> 1][nf & 1],
                                       b[nf >> 1][2 + (nf & 1)] };
                    mma16816(acc[mf][nf], a[mf], bf);
                }
        }
        __syncthreads();
        if (c + 2 < nch) issue(st);
        asm volatile("cp.async.commit_group;" ::: "memory");
    }

    if (EPI == 0) {
        #pragma unroll
        for (int mf = 0; mf < 2; mf++) {
            const int r0 = m0 + warpM * 32 + mf * 16 + (lane >> 2);
            float rs0 = 0.f, rs1 = 0.f;
            #pragma unroll
            for (int nf = 0; nf < 4; nf++) {
                const int cl = warpN * 32 + nf * 8 + (lane & 3) * 2;  // local col
                const int cb = n0 + cl;
                // p = exp(10*cos - 10) * PSCALE  (scale cancels in normalization)
                const float e0 = __expf(acc[mf][nf][0] * 10.f - 10.f) * PSCALE;
                const float e1 = __expf(acc[mf][nf][1] * 10.f - 10.f) * PSCALE;
                const float e2 = __expf(acc[mf][nf][2] * 10.f - 10.f) * PSCALE;
                const float e3 = __expf(acc[mf][nf][3] * 10.f - 10.f) * PSCALE;
                rs0 += e0 + e1;  rs1 += e2 + e3;
                // fold ||emb_v|| into stored probs (GEMM2 uses normalized emb)
                const float w0 = sNorm[cl], w1 = sNorm[cl + 1];
                *(uint32_t*)&g_probs[(size_t)r0 * VV + cb] = pack2h(e0 * w0, e1 * w1);
                *(uint32_t*)&g_probs[(size_t)(r0 + 8) * VV + cb] = pack2h(e2 * w0, e3 * w1);
            }
            rs0 += __shfl_xor_sync(0xffffffffu, rs0, 1);
            rs0 += __shfl_xor_sync(0xffffffffu, rs0, 2);
            rs1 += __shfl_xor_sync(0xffffffffu, rs1, 1);
            rs1 += __shfl_xor_sync(0xffffffffu, rs1, 2);
            if ((lane & 3) == 0) {
                atomicAdd(&g_rowsum[r0],     rs0);
                atomicAdd(&g_rowsum[r0 + 8], rs1);
            }
        }
    } else {
        #pragma unroll
        for (int mf = 0; mf < 2; mf++) {
            const int r0 = m0 + warpM * 32 + mf * 16 + (lane >> 2);
            const float s0 = (EPI == 1) ? 1.f / g_rowsum[r0]     : 1.f;
            const float s1 = (EPI == 1) ? 1.f / g_rowsum[r0 + 8] : 1.f;
            #pragma unroll
            for (int nf = 0; nf < 4; nf++) {
                const int cb = n0 + warpN * 32 + nf * 8 + (lane & 3) * 2;
                atomicAdd(&outf[(size_t)r0 * TT + cb],           acc[mf][nf][0] * s0);
                atomicAdd(&outf[(size_t)r0 * TT + cb + 1],       acc[mf][nf][1] * s0);
                atomicAdd(&outf[(size_t)(r0 + 8) * TT + cb],     acc[mf][nf][2] * s1);
                atomicAdd(&outf[(size_t)(r0 + 8) * TT + cb + 1], acc[mf][nf][3] * s1);
            }
        }
    }
}

// fp32 -> fp16 streaming pack, TWO tensors in one launch (audio then W)
__global__ __launch_bounds__(512)
void pack_f16_2(const float* __restrict__ s0, __half* __restrict__ d0, int n0_4,
                const float* __restrict__ s1, __half* __restrict__ d1, int n1_4)
{
    const int total = n0_4 + n1_4;
    for (int i = blockIdx.x * blockDim.x + threadIdx.x; i < total;
         i += gridDim.x * blockDim.x) {
        const float4 v = (i < n0_4) ? ((const float4*)s0)[i]
                                    : ((const float4*)s1)[i - n0_4];
        const uint2 pk = make_uint2(pack2h(v.x, v.y), pack2h(v.z, v.w));
        if (i < n0_4) ((uint2*)d0)[i] = pk;
        else          ((uint2*)d1)[i - n0_4] = pk;
    }
}

// kw rows: add bias, L2-normalize, write fp16
__global__ void kw_norm_pack(const float* __restrict__ bias)
{
    const int w    = (blockIdx.x * blockDim.x + threadIdx.x) >> 5;
    const int lane = threadIdx.x & 31;
    if (w >= BN) return;
    const float4* row = (const float4*)(g_kw + (size_t)w * TT);
    const float4* b4  = (const float4*)bias;
    float4 v[4];
    float ss = 0.f;
    #pragma unroll
    for (int q = 0; q < 4; q++) {
        v[q] = row[lane + 32 * q];
        const float4 bb = b4[lane + 32 * q];
        v[q].x += bb.x; v[q].y += bb.y; v[q].z += bb.z; v[q].w += bb.w;
        ss += v[q].x * v[q].x + v[q].y * v[q].y + v[q].z * v[q].z + v[q].w * v[q].w;
    }
    #pragma unroll
    for (int o = 16; o > 0; o >>= 1) ss += __shfl_xor_sync(0xffffffffu, ss, o);
    const float inv = 1.f / fmaxf(sqrtf(ss), 1e-8f);
    #pragma unroll
    for (int q = 0; q < 4; q++) {
        const int e0 = (lane + 32 * q) * 4;
        const uint2 pk = make_uint2(pack2h(v[q].x * inv, v[q].y * inv),
                                    pack2h(v[q].z * inv, v[q].w * inv));
        *(uint2*)&g_kwH[(size_t)w * TT + e0] = pk;
    }
}

// emb prep: one warp per vocab row; read fp32 once,
// write normalized fp16 (embH) + row norm (g_norm).
__global__ __launch_bounds__(512)
void emb_prep(const float* __restrict__ emb)
{
    const int w    = (blockIdx.x * blockDim.x + threadIdx.x) >> 5;
    const int lane = threadIdx.x & 31;
    if (w >= VV) return;
    const float4* row = (const float4*)(emb + (size_t)w * TT);
    float4 v[4];
    float ss = 0.f;
    #pragma unroll
    for (int q = 0; q < 4; q++) {
        v[q] = row[lane + 32 * q];
        ss += v[q].x * v[q].x + v[q].y * v[q].y + v[q].z * v[q].z + v[q].w * v[q].w;
    }
    #pragma unroll
    for (int o = 16; o > 0; o >>= 1) ss += __shfl_xor_sync(0xffffffffu, ss, o);
    const float nrm = sqrtf(ss);
    const float inv = 1.f / fmaxf(nrm, 1e-8f);
    if (lane == 0) g_norm[w] = nrm;
    #pragma unroll
    for (int q = 0; q < 4; q++) {
        const int e0 = (lane + 32 * q) * 4;
        const uint2 pk = make_uint2(pack2h(v[q].x * inv, v[q].y * inv),
                                    pack2h(v[q].z * inv, v[q].w * inv));
        *(uint2*)&g_embH[(size_t)w * TT + e0] = pk;
    }
}

// =============================================================================
extern "C" void kernel_launch(void* const* d_in, const int* in_sizes, int n_in,
                              void* d_out, int out_size)
{
    const float* audio = (const float*)d_in[0];
    const float* W     = (const float*)d_in[1];
    const float* bias  = (const float*)d_in[2];
    const float* emb   = (const float*)d_in[3];
    float* out = (float*)d_out;

    // one-time resource setup (no device memory; identical GPU work every call)
    static cudaStream_t s2 = nullptr;
    static cudaEvent_t evFork = nullptr, evJoin = nullptr;
    if (!s2) {
        cudaStreamCreateWithFlags(&s2, cudaStreamNonBlocking);
        cudaEventCreateWithFlags(&evFork, cudaEventDisableTiming);
        cudaEventCreateWithFlags(&evJoin, cudaEventDisableTiming);
        cudaFuncSetAttribute(mma_gemm<0>, cudaFuncAttributeMaxDynamicSharedMemorySize, SMEMSZ);
        cudaFuncSetAttribute(mma_gemm<1>, cudaFuncAttributeMaxDynamicSharedMemorySize, SMEMSZ);
        cudaFuncSetAttribute(mma_gemm<2>, cudaFuncAttributeMaxDynamicSharedMemorySize, SMEMSZ);
    }

    float *kw, *rowsum;
    __half *audioH, *WH;
    cudaGetSymbolAddress((void**)&kw,     g_kw);
    cudaGetSymbolAddress((void**)&rowsum, g_rowsum);
    cudaGetSymbolAddress((void**)&audioH, g_audioH);
    cudaGetSymbolAddress((void**)&WH,     g_WH);

    // ---- fork: emb_prep runs concurrently on side stream ----
    cudaEventRecord(evFork, 0);
    cudaStreamWaitEvent(s2, evFork, 0);
    emb_prep<<<VV / 16, 512, 0, s2>>>(emb);
    cudaEventRecord(evJoin, s2);

    // ---- main-stream chain: packs -> proj -> kw_norm (+ memsets) ----
    cudaMemsetAsync(kw,     0, (size_t)BN * TT * sizeof(float), 0);
    cudaMemsetAsync(rowsum, 0, BN * sizeof(float), 0);
    cudaMemsetAsync(out,    0, (size_t)out_size * sizeof(float), 0);
    pack_f16_2<<<304, 512>>>(audio, audioH, BN * DD / 4, W, WH, DD * TT / 4);
    // projection on tensor path: x = n-tiles (4), y = m-tiles (8), z = split-K (4)
    mma_gemm<2><<<dim3(TT / 128, BN / 128, 4), 512, SMEMSZ>>>(kw);
    kw_norm_pack<<<BN / 8, 256>>>(bias);

    // ---- join, then the two floor-bound GEMMs ----
    cudaStreamWaitEvent(0, evJoin, 0);
    // GEMM1: logits + exp epilogue
    mma_gemm<0><<<dim3(BN / 128, VV / 128), 512, SMEMSZ>>>(nullptr);
    // GEMM2: x = n-tiles (4), y = m-tiles (8), z = split-K (9)
    mma_gemm<1><<<dim3(TT / 128, BN / 128, 9), 512, SMEMSZ>>>(out);
}